// round 11
// baseline (speedup 1.0000x reference)
#include <cuda_runtime.h>
#include <cuda_fp8.h>
#include <cuda_fp16.h>
#include <cstdint>

// Quantize_55327768707293
// x: [8192, 8192] fp32. Tiled 128x128. Per tile:
//   absmax -> e = ceil(log2(absmax)) (absmax==0 -> e=0)
//   scale = 2^(e-1)   (MAX_EXP = 1)
//   xq = fp32(fp8_e5m2(x * 2^(1-e)))
// Output: [xq (8192*8192 fp32) | scale (64*64 fp32)]
//
// R11: R10 body (register-staged tile, plain cached ld/st, one barrier,
// REDUX reductions) at 3 CTAs/SM instead of 2. R6's earlier 3-CTA probe was
// confounded by ldcs/stcs hints (independently measured ~1us cost); with
// plain ld/st, a third independent sync domain per SM should shrink the
// windows where every resident CTA is in its reduce/store phase and DRAM
// reads idle.

constexpr int N        = 8192;
constexpr int B        = 128;
constexpr int TILES    = N / B;          // 64
constexpr int THREADS  = 512;            // 16 warps
constexpr int NWARPS   = THREADS / 32;
constexpr int SWEEPS   = B / NWARPS;     // 8 float4 per thread (32 floats)
constexpr int ROW4     = N / 4;
constexpr int CTAS_PER_SM = 3;

__device__ __forceinline__ float2 fakequant2(float a, float b) {
    // fp32 -> e5m2 (RNE, hardware cvt) -> half (exact) -> fp32 (exact)
    float2 in = make_float2(a, b);
    __nv_fp8x2_storage_t q = __nv_cvt_float2_to_fp8x2(in, __NV_SATFINITE, __NV_E5M2);
    __half2_raw hr = __nv_cvt_fp8x2_to_halfraw2(q, __NV_E5M2);
    __half2 h = *reinterpret_cast<__half2*>(&hr);
    return __half22float2(h);
}

__device__ __forceinline__ uint32_t absbits(float x) {
    return __float_as_uint(x) & 0x7fffffffu;   // |x| bit pattern; monotone for max
}

__global__ void __launch_bounds__(THREADS, CTAS_PER_SM)
quantize_tile_kernel(const float* __restrict__ x,
                     float* __restrict__ out,
                     float* __restrict__ scale_out) {
    const int tx   = blockIdx.x;          // tile col
    const int ty   = blockIdx.y;          // tile row
    const int warp = threadIdx.x >> 5;
    const int lane = threadIdx.x & 31;

    const size_t tile_base = (size_t)ty * B * N + (size_t)tx * B;
    const float4* __restrict__ xin = reinterpret_cast<const float4*>(x + tile_base);
    float4* __restrict__ oq        = reinterpret_cast<float4*>(out + tile_base);

    // ---- Load whole tile into registers; front-batched LDG.128 for MLP ----
    float4 v[SWEEPS];
    #pragma unroll
    for (int i = 0; i < SWEEPS; i++) {
        const int row = warp + i * NWARPS;
        v[i] = xin[(size_t)row * ROW4 + lane];
    }

    // ---- Local absmax as u32 bit-pattern max ----
    uint32_t am = 0u;
    #pragma unroll
    for (int i = 0; i < SWEEPS; i++) {
        am = max(am, max(max(absbits(v[i].x), absbits(v[i].y)),
                         max(absbits(v[i].z), absbits(v[i].w))));
    }

    // ---- Block reduce: REDUX warp max -> smem -> ONE barrier -> REDUX ----
    am = __reduce_max_sync(0xffffffffu, am);

    __shared__ uint32_t smax[NWARPS];
    if (lane == 0) smax[warp] = am;
    __syncthreads();
    uint32_t ab = (lane < NWARPS) ? smax[lane] : 0u;
    ab = __reduce_max_sync(0xffffffffu, ab);
    const float a = __uint_as_float(ab);

    // ---- e = ceil(log2(a)), exact; a==0 -> e=0 ----
    int e = 0;
    if (a > 0.0f) {
        int k;
        float m = frexpf(a, &k);          // a = m * 2^k, m in [0.5, 1)
        e = (m == 0.5f) ? (k - 1) : k;    // exact power of two -> k-1
    }
    const float inv = ldexpf(1.0f, 1 - e);    // 2^(MAX_EXP - e), exact

    if (threadIdx.x == 0)
        scale_out[ty * TILES + tx] = ldexpf(1.0f, e - 1);

    // ---- Quantize from registers, store ----
    #pragma unroll
    for (int i = 0; i < SWEEPS; i++) {
        const int row = warp + i * NWARPS;
        float2 xy = fakequant2(v[i].x * inv, v[i].y * inv);
        float2 zw = fakequant2(v[i].z * inv, v[i].w * inv);
        oq[(size_t)row * ROW4 + lane] = make_float4(xy.x, xy.y, zw.x, zw.y);
    }
}

extern "C" void kernel_launch(void* const* d_in, const int* in_sizes, int n_in,
                              void* d_out, int out_size) {
    (void)in_sizes; (void)n_in; (void)out_size;
    const float* x = (const float*)d_in[0];
    float* out = (float*)d_out;
    float* scale_out = out + (size_t)N * N;

    dim3 grid(TILES, TILES);
    quantize_tile_kernel<<<grid, THREADS>>>(x, out, scale_out);
}

// round 12
// speedup vs baseline: 1.0909x; 1.0909x over previous
#include <cuda_runtime.h>
#include <cuda_fp8.h>
#include <cuda_fp16.h>
#include <cstdint>

// Quantize_55327768707293
// x: [8192, 8192] fp32. Tiled 128x128. Per tile:
//   absmax -> e = ceil(log2(absmax)) (absmax==0 -> e=0)
//   scale = 2^(e-1)   (MAX_EXP = 1)
//   xq = fp32(fp8_e5m2(x * 2^(1-e)))
// Output: [xq (8192*8192 fp32) | scale (64*64 fp32)]
//
// R12: R10 (best: 4096 CTAs, 512 thr, 2 CTAs/SM, register staging, plain
// cached ops, one-barrier REDUX reduce) with 256-bit LDG/STG (.v8.b32,
// supported on sm_103a). Same bytes + regs, half the LSU issue slots and
// L1tex queue entries; 4 front-batched LDG.256 reach full per-thread MLP.
// Each thread owns 8 consecutive floats; half-warp = one 512B row segment.

constexpr int N        = 8192;
constexpr int B        = 128;
constexpr int TILES    = N / B;          // 64
constexpr int THREADS  = 512;            // 16 warps
constexpr int NWARPS   = THREADS / 32;
constexpr int CHUNKS   = B * B / 8;      // 2048 8-float chunks per tile
constexpr int CPT      = CHUNKS / THREADS;  // 4 chunks (32 floats) per thread
constexpr int CROW     = B / 8;          // 16 chunks per row

__device__ __forceinline__ void ldg256(const float* p, float (&o)[8]) {
    asm volatile("ld.global.v8.b32 {%0,%1,%2,%3,%4,%5,%6,%7}, [%8];"
                 : "=f"(o[0]), "=f"(o[1]), "=f"(o[2]), "=f"(o[3]),
                   "=f"(o[4]), "=f"(o[5]), "=f"(o[6]), "=f"(o[7])
                 : "l"(p));
}

__device__ __forceinline__ void stg256(float* p, const float (&v)[8]) {
    asm volatile("st.global.v8.b32 [%0], {%1,%2,%3,%4,%5,%6,%7,%8};"
                 :: "l"(p),
                    "f"(v[0]), "f"(v[1]), "f"(v[2]), "f"(v[3]),
                    "f"(v[4]), "f"(v[5]), "f"(v[6]), "f"(v[7]));
}

__device__ __forceinline__ float2 fakequant2(float a, float b) {
    // fp32 -> e5m2 (RNE, hardware cvt) -> half (exact) -> fp32 (exact)
    float2 in = make_float2(a, b);
    __nv_fp8x2_storage_t q = __nv_cvt_float2_to_fp8x2(in, __NV_SATFINITE, __NV_E5M2);
    __half2_raw hr = __nv_cvt_fp8x2_to_halfraw2(q, __NV_E5M2);
    __half2 h = *reinterpret_cast<__half2*>(&hr);
    return __half22float2(h);
}

__device__ __forceinline__ uint32_t absbits(float x) {
    return __float_as_uint(x) & 0x7fffffffu;   // |x| bit pattern; monotone for max
}

__global__ void __launch_bounds__(THREADS, 2)
quantize_tile_kernel(const float* __restrict__ x,
                     float* __restrict__ out,
                     float* __restrict__ scale_out) {
    const int tx   = blockIdx.x;          // tile col
    const int ty   = blockIdx.y;          // tile row
    const int tid  = threadIdx.x;
    const int warp = tid >> 5;
    const int lane = tid & 31;

    const size_t tile_base = (size_t)ty * B * N + (size_t)tx * B;
    const float* __restrict__ xin = x + tile_base;
    float* __restrict__ oq        = out + tile_base;

    // ---- Load whole tile into registers; 4 front-batched LDG.256 ----
    float v[CPT][8];
    #pragma unroll
    for (int k = 0; k < CPT; k++) {
        const int c    = tid + k * THREADS;
        const int row  = c / CROW;
        const int col8 = (c % CROW) * 8;
        ldg256(xin + (size_t)row * N + col8, v[k]);
    }

    // ---- Local absmax as u32 bit-pattern max ----
    uint32_t am = 0u;
    #pragma unroll
    for (int k = 0; k < CPT; k++) {
        uint32_t m0 = max(max(absbits(v[k][0]), absbits(v[k][1])),
                          max(absbits(v[k][2]), absbits(v[k][3])));
        uint32_t m1 = max(max(absbits(v[k][4]), absbits(v[k][5])),
                          max(absbits(v[k][6]), absbits(v[k][7])));
        am = max(am, max(m0, m1));
    }

    // ---- Block reduce: REDUX warp max -> smem -> ONE barrier -> REDUX ----
    am = __reduce_max_sync(0xffffffffu, am);

    __shared__ uint32_t smax[NWARPS];
    if (lane == 0) smax[warp] = am;
    __syncthreads();
    uint32_t ab = (lane < NWARPS) ? smax[lane] : 0u;
    ab = __reduce_max_sync(0xffffffffu, ab);
    const float a = __uint_as_float(ab);

    // ---- e = ceil(log2(a)), exact; a==0 -> e=0 ----
    int e = 0;
    if (a > 0.0f) {
        int k;
        float m = frexpf(a, &k);          // a = m * 2^k, m in [0.5, 1)
        e = (m == 0.5f) ? (k - 1) : k;    // exact power of two -> k-1
    }
    const float inv = ldexpf(1.0f, 1 - e);    // 2^(MAX_EXP - e), exact

    if (tid == 0)
        scale_out[ty * TILES + tx] = ldexpf(1.0f, e - 1);

    // ---- Quantize from registers, STG.256 stores ----
    #pragma unroll
    for (int k = 0; k < CPT; k++) {
        const int c    = tid + k * THREADS;
        const int row  = c / CROW;
        const int col8 = (c % CROW) * 8;
        float q[8];
        #pragma unroll
        for (int j = 0; j < 4; j++) {
            float2 p = fakequant2(v[k][2*j] * inv, v[k][2*j+1] * inv);
            q[2*j]   = p.x;
            q[2*j+1] = p.y;
        }
        stg256(oq + (size_t)row * N + col8, q);
    }
}

extern "C" void kernel_launch(void* const* d_in, const int* in_sizes, int n_in,
                              void* d_out, int out_size) {
    (void)in_sizes; (void)n_in; (void)out_size;
    const float* x = (const float*)d_in[0];
    float* out = (float*)d_out;
    float* scale_out = out + (size_t)N * N;

    dim3 grid(TILES, TILES);
    quantize_tile_kernel<<<grid, THREADS>>>(x, out, scale_out);
}

// round 13
// speedup vs baseline: 1.0998x; 1.0082x over previous
#include <cuda_runtime.h>
#include <cuda_fp8.h>
#include <cuda_fp16.h>
#include <cstdint>

// Quantize_55327768707293
// x: [8192, 8192] fp32. Tiled 128x128. Per tile:
//   absmax -> e = ceil(log2(absmax)) (absmax==0 -> e=0)
//   scale = 2^(e-1)   (MAX_EXP = 1)
//   xq = fp32(fp8_e5m2(x * 2^(1-e)))
// Output: [xq (8192*8192 fp32) | scale (64*64 fp32)]
//
// R13 (terminal form): R10 — the measured optimum across 12 rounds:
//   4096 CTAs (one per tile), 512 threads, 2 CTAs/SM, whole tile staged in
//   registers via 8 front-batched LDG.128/thread (128KB outstanding/SM),
//   plain cached ld/st, one-barrier REDUX block-max.
// Micro-trim vs R10: branchless integer exponent (ceil(log2) on the fp32
// bit pattern) replaces frexpf+branch on the post-barrier serial critical
// path that gates all stores.

constexpr int N        = 8192;
constexpr int B        = 128;
constexpr int TILES    = N / B;          // 64
constexpr int THREADS  = 512;            // 16 warps
constexpr int NWARPS   = THREADS / 32;
constexpr int SWEEPS   = B / NWARPS;     // 8 float4 per thread (32 floats)
constexpr int ROW4     = N / 4;

__device__ __forceinline__ float2 fakequant2(float a, float b) {
    // fp32 -> e5m2 (RNE, hardware cvt) -> half (exact) -> fp32 (exact)
    float2 in = make_float2(a, b);
    __nv_fp8x2_storage_t q = __nv_cvt_float2_to_fp8x2(in, __NV_SATFINITE, __NV_E5M2);
    __half2_raw hr = __nv_cvt_fp8x2_to_halfraw2(q, __NV_E5M2);
    __half2 h = *reinterpret_cast<__half2*>(&hr);
    return __half22float2(h);
}

__device__ __forceinline__ uint32_t absbits(float x) {
    return __float_as_uint(x) & 0x7fffffffu;   // |x| bit pattern; monotone for max
}

// e = ceil(log2(value(ab))) for ab = |a| bit pattern; ab==0 -> 0. Exact.
__device__ __forceinline__ int ceil_log2_bits(uint32_t ab) {
    if (ab == 0u) return 0;
    const uint32_t man = ab & 0x7fffffu;
    const int ef = (int)(ab >> 23);
    if (ef != 0)                                    // normal
        return ef - 127 + (man != 0u);
    // subnormal: value = man * 2^-149
    const int fl = 31 - __clz(man);                 // floor(log2(man))
    return fl - 149 + ((man & (man - 1u)) != 0u);
}

__global__ void __launch_bounds__(THREADS, 2)
quantize_tile_kernel(const float* __restrict__ x,
                     float* __restrict__ out,
                     float* __restrict__ scale_out) {
    const int tx   = blockIdx.x;          // tile col
    const int ty   = blockIdx.y;          // tile row
    const int warp = threadIdx.x >> 5;
    const int lane = threadIdx.x & 31;

    const size_t tile_base = (size_t)ty * B * N + (size_t)tx * B;
    const float4* __restrict__ xin = reinterpret_cast<const float4*>(x + tile_base);
    float4* __restrict__ oq        = reinterpret_cast<float4*>(out + tile_base);

    // ---- Load whole tile into registers; 8 front-batched LDG.128 ----
    float4 v[SWEEPS];
    #pragma unroll
    for (int i = 0; i < SWEEPS; i++) {
        const int row = warp + i * NWARPS;
        v[i] = xin[(size_t)row * ROW4 + lane];
    }

    // ---- Local absmax as u32 bit-pattern max ----
    uint32_t am = 0u;
    #pragma unroll
    for (int i = 0; i < SWEEPS; i++) {
        am = max(am, max(max(absbits(v[i].x), absbits(v[i].y)),
                         max(absbits(v[i].z), absbits(v[i].w))));
    }

    // ---- Block reduce: REDUX warp max -> smem -> ONE barrier -> REDUX ----
    am = __reduce_max_sync(0xffffffffu, am);

    __shared__ uint32_t smax[NWARPS];
    if (lane == 0) smax[warp] = am;
    __syncthreads();
    uint32_t ab = (lane < NWARPS) ? smax[lane] : 0u;
    ab = __reduce_max_sync(0xffffffffu, ab);

    // ---- e = ceil(log2(absmax)) via branchless-ish bit math ----
    const int e = ceil_log2_bits(ab);
    const float inv = ldexpf(1.0f, 1 - e);    // 2^(MAX_EXP - e), exact

    if (threadIdx.x == 0)
        scale_out[ty * TILES + tx] = ldexpf(1.0f, e - 1);

    // ---- Quantize from registers, store ----
    #pragma unroll
    for (int i = 0; i < SWEEPS; i++) {
        const int row = warp + i * NWARPS;
        float2 xy = fakequant2(v[i].x * inv, v[i].y * inv);
        float2 zw = fakequant2(v[i].z * inv, v[i].w * inv);
        oq[(size_t)row * ROW4 + lane] = make_float4(xy.x, xy.y, zw.x, zw.y);
    }
}

extern "C" void kernel_launch(void* const* d_in, const int* in_sizes, int n_in,
                              void* d_out, int out_size) {
    (void)in_sizes; (void)n_in; (void)out_size;
    const float* x = (const float*)d_in[0];
    float* out = (float*)d_out;
    float* scale_out = out + (size_t)N * N;

    dim3 grid(TILES, TILES);
    quantize_tile_kernel<<<grid, THREADS>>>(x, out, scale_out);
}